// round 2
// baseline (speedup 1.0000x reference)
#include <cuda_runtime.h>
#include <math.h>

// Problem constants
#define LNUM 4
#define BB   64
#define TT   256
#define HH   1024
#define DD   1024
#define G4   4096   // 4*H
#define NBLK 128    // persistent-kernel grid (must be <= 148 SMs for co-residency)

// ---------------- scratch (device globals; no runtime allocation) ----------------
__device__ float g_gx[(size_t)TT * BB * G4];        // [t][b][4H]
__device__ float g_act[2][(size_t)BB * TT * HH];    // layer activation ping-pong
__device__ float g_h[BB * HH];
__device__ float g_c[BB * HH];
__device__ float g_part[(size_t)8 * BB * G4];       // k-split partials
__device__ unsigned long long g_barctr;             // zero-initialized at module load

// ---------------- packed fp32x2 (FFMA2) helpers ----------------
__device__ __forceinline__ unsigned long long pk2(float lo, float hi) {
    unsigned long long r;
    asm("mov.b64 %0, {%1, %2};" : "=l"(r) : "f"(lo), "f"(hi));
    return r;
}
__device__ __forceinline__ void upk2(unsigned long long v, float& lo, float& hi) {
    asm("mov.b64 {%0, %1}, %2;" : "=f"(lo), "=f"(hi) : "l"(v));
}
__device__ __forceinline__ void fma2(unsigned long long& acc, unsigned long long a, unsigned long long b) {
    asm("fma.rn.f32x2 %0, %1, %2, %0;" : "+l"(acc) : "l"(a), "l"(b));
}

__device__ __forceinline__ float sigmoidf_(float x) { return 1.0f / (1.0f + expf(-x)); }

// ---------------- software grid barrier (monotonic ticket, replay-safe) ----------------
__device__ __forceinline__ void grid_barrier() {
    __syncthreads();
    if (threadIdx.x == 0) {
        __threadfence();
        unsigned long long ticket = atomicAdd(&g_barctr, 1ull);
        unsigned long long target = (ticket / NBLK + 1ull) * NBLK;
        while (*(volatile unsigned long long*)&g_barctr < target) {
            __nanosleep(64);
        }
        __threadfence();
    }
    __syncthreads();
}

// ---------------- generic NT GEMM: C[m,n] = sum_k A[m,k]*B[n,k] (+bias) ----------------
// MODE 0: proj -> C[m*N + n] + bias
// MODE 1: gx   -> C[((t*BB + b)*G4) + n] + bias, with m = b*TT + t
template<int BM, int BN, int MT, int NT, int MODE>
__global__ void __launch_bounds__(256)
gemm_nt(const float* __restrict__ A, const float* __restrict__ B,
        const float* __restrict__ bias, float* __restrict__ C, int K)
{
    constexpr int TM = BM / MT;
    constexpr int TN = BN / NT;
    constexpr int BK = 16;
    static_assert(MT * NT == 256, "256 threads");
    static_assert(TM == 8 && TN == 8, "fixed micro-tile");

    __shared__ __align__(16) float As[BK][BM];
    __shared__ __align__(16) float Bs[BK][BN];

    const int tid = threadIdx.x;
    const int tmi = tid / NT;
    const int tni = tid % NT;
    const int m0 = blockIdx.x * BM;
    const int n0 = blockIdx.y * BN;

    unsigned long long acc[TM / 2][TN];
#pragma unroll
    for (int i = 0; i < TM / 2; i++)
#pragma unroll
        for (int j = 0; j < TN; j++) acc[i][j] = 0ull;

#pragma unroll 1
    for (int kb = 0; kb < K; kb += BK) {
        for (int s = tid; s < BM * 4; s += 256) {
            int r = s >> 2, c4 = (s & 3) << 2;
            const float4 v = *reinterpret_cast<const float4*>(A + (size_t)(m0 + r) * K + kb + c4);
            As[c4 + 0][r] = v.x; As[c4 + 1][r] = v.y; As[c4 + 2][r] = v.z; As[c4 + 3][r] = v.w;
        }
        for (int s = tid; s < BN * 4; s += 256) {
            int r = s >> 2, c4 = (s & 3) << 2;
            const float4 v = *reinterpret_cast<const float4*>(B + (size_t)(n0 + r) * K + kb + c4);
            Bs[c4 + 0][r] = v.x; Bs[c4 + 1][r] = v.y; Bs[c4 + 2][r] = v.z; Bs[c4 + 3][r] = v.w;
        }
        __syncthreads();

#pragma unroll
        for (int kk = 0; kk < BK; kk++) {
            unsigned long long af[TM / 2];
            unsigned long long bsp[TN];
#pragma unroll
            for (int i = 0; i < TM / 2; i++)
                af[i] = *reinterpret_cast<const unsigned long long*>(&As[kk][tmi * TM + 2 * i]);
#pragma unroll
            for (int j = 0; j < TN; j++) {
                float bv = Bs[kk][tni * TN + j];
                bsp[j] = pk2(bv, bv);
            }
#pragma unroll
            for (int i = 0; i < TM / 2; i++)
#pragma unroll
                for (int j = 0; j < TN; j++)
                    fma2(acc[i][j], af[i], bsp[j]);
        }
        __syncthreads();
    }

    float bq[TN];
#pragma unroll
    for (int j = 0; j < TN; j++) bq[j] = bias[n0 + tni * TN + j];

#pragma unroll
    for (int i = 0; i < TM / 2; i++) {
        float lo[TN], hi[TN];
#pragma unroll
        for (int j = 0; j < TN; j++) {
            upk2(acc[i][j], lo[j], hi[j]);
            lo[j] += bq[j]; hi[j] += bq[j];
        }
        const int mA = m0 + tmi * TM + 2 * i;
        const int mBr = mA + 1;
        const int ncol = n0 + tni * TN;

        size_t baseA, baseB;
        if (MODE == 0) {
            const size_t ldc = (size_t)gridDim.y * BN;
            baseA = (size_t)mA * ldc + ncol;
            baseB = (size_t)mBr * ldc + ncol;
        } else {
            int tA = mA & (TT - 1), bA = mA >> 8;
            int tB = mBr & (TT - 1), bBa = mBr >> 8;
            baseA = ((size_t)(tA * BB + bA)) * G4 + ncol;
            baseB = ((size_t)(tB * BB + bBa)) * G4 + ncol;
        }
        float4 a0 = {lo[0], lo[1], lo[2], lo[3]}, a1 = {lo[4], lo[5], lo[6], lo[7]};
        float4 b0 = {hi[0], hi[1], hi[2], hi[3]}, b1 = {hi[4], hi[5], hi[6], hi[7]};
        *reinterpret_cast<float4*>(C + baseA) = a0;
        *reinterpret_cast<float4*>(C + baseA + 4) = a1;
        *reinterpret_cast<float4*>(C + baseB) = b0;
        *reinterpret_cast<float4*>(C + baseB + 4) = b1;
    }
}

// ---------------- persistent per-layer recurrence kernel ----------------
// grid = 128 blocks x 256 threads, all co-resident. Per timestep:
//   phase 1: block (ntile, kz) computes partial[kz] of h @ Whh^T over a 64x256 tile, K-chunk 128
//   phase 2: each block reduces partials + gate math for its 512 (b,j) elements
__global__ void __launch_bounds__(256, 1)
layer_recurrence(const float* __restrict__ gx, const float* __restrict__ Whh,
                 float* __restrict__ h, float* __restrict__ c,
                 float* __restrict__ part, float* __restrict__ act_out)
{
    __shared__ __align__(16) float As[16][64];
    __shared__ __align__(16) float Bs[16][256];

    const int tid = threadIdx.x;
    const int bid = blockIdx.x;
    const int tmi = tid >> 5;          // 0..7 -> rows tmi*8..+7
    const int tni = tid & 31;          // 0..31 -> cols tni*8..+7
    const int n0 = (bid & 15) * 256;   // N-tile origin in 4096
    const int kz = bid >> 4;           // K-split 0..7
    const int k0 = kz * 128;

    // gates-phase element assignment: 2 consecutive j's per thread
    const int gbase = bid * 512 + tid * 2;   // 0..65535
    const int gb = gbase >> 10;              // batch row
    const int gj = gbase & 1023;             // hidden index

#pragma unroll 1
    for (int t = 0; t < TT; t++) {
        // ---- phase 1: partial GEMM ----
        unsigned long long acc[4][8];
#pragma unroll
        for (int i = 0; i < 4; i++)
#pragma unroll
            for (int j = 0; j < 8; j++) acc[i][j] = 0ull;

#pragma unroll 1
        for (int kb = 0; kb < 128; kb += 16) {
            {
                int r = tid >> 2, c4 = (tid & 3) << 2;
                float4 v = __ldcg(reinterpret_cast<const float4*>(h + (size_t)r * HH + k0 + kb + c4));
                As[c4 + 0][r] = v.x; As[c4 + 1][r] = v.y; As[c4 + 2][r] = v.z; As[c4 + 3][r] = v.w;
            }
#pragma unroll
            for (int s = 0; s < 4; s++) {
                int ss = tid + s * 256;
                int r = ss >> 2, c4 = (ss & 3) << 2;
                float4 v = *reinterpret_cast<const float4*>(Whh + (size_t)(n0 + r) * HH + k0 + kb + c4);
                Bs[c4 + 0][r] = v.x; Bs[c4 + 1][r] = v.y; Bs[c4 + 2][r] = v.z; Bs[c4 + 3][r] = v.w;
            }
            __syncthreads();

#pragma unroll
            for (int kk = 0; kk < 16; kk++) {
                unsigned long long af[4], bsp[8];
#pragma unroll
                for (int i = 0; i < 4; i++)
                    af[i] = *reinterpret_cast<const unsigned long long*>(&As[kk][tmi * 8 + 2 * i]);
#pragma unroll
                for (int j = 0; j < 8; j++) {
                    float bv = Bs[kk][tni * 8 + j];
                    bsp[j] = pk2(bv, bv);
                }
#pragma unroll
                for (int i = 0; i < 4; i++)
#pragma unroll
                    for (int j = 0; j < 8; j++)
                        fma2(acc[i][j], af[i], bsp[j]);
            }
            __syncthreads();
        }

        // write partials
#pragma unroll
        for (int i = 0; i < 4; i++) {
            float lo[8], hi[8];
#pragma unroll
            for (int j = 0; j < 8; j++) upk2(acc[i][j], lo[j], hi[j]);
            int mA = tmi * 8 + 2 * i;
            size_t baseA = ((size_t)kz * BB + mA) * G4 + n0 + tni * 8;
            size_t baseB = baseA + G4;  // next row
            float4 a0 = {lo[0], lo[1], lo[2], lo[3]}, a1 = {lo[4], lo[5], lo[6], lo[7]};
            float4 b0 = {hi[0], hi[1], hi[2], hi[3]}, b1 = {hi[4], hi[5], hi[6], hi[7]};
            *reinterpret_cast<float4*>(part + baseA) = a0;
            *reinterpret_cast<float4*>(part + baseA + 4) = a1;
            *reinterpret_cast<float4*>(part + baseB) = b0;
            *reinterpret_cast<float4*>(part + baseB + 4) = b1;
        }

        grid_barrier();

        // ---- phase 2: reduce partials + gates ----
        {
            const float* gxt = gx + (size_t)t * BB * G4;
            float gs[4][2];
#pragma unroll
            for (int q = 0; q < 4; q++) {
                size_t off = (size_t)gb * G4 + q * HH + gj;
                float2 s = *reinterpret_cast<const float2*>(gxt + off);
                gs[q][0] = s.x; gs[q][1] = s.y;
#pragma unroll
                for (int z = 0; z < 8; z++) {
                    float2 p = __ldcg(reinterpret_cast<const float2*>(
                        part + ((size_t)z * BB + gb) * G4 + q * HH + gj));
                    gs[q][0] += p.x; gs[q][1] += p.y;
                }
            }
            float2 cv = __ldcg(reinterpret_cast<const float2*>(c + (size_t)gb * HH + gj));
            float cn0 = sigmoidf_(gs[1][0]) * cv.x + sigmoidf_(gs[0][0]) * tanhf(gs[2][0]);
            float cn1 = sigmoidf_(gs[1][1]) * cv.y + sigmoidf_(gs[0][1]) * tanhf(gs[2][1]);
            float hn0 = sigmoidf_(gs[3][0]) * tanhf(cn0);
            float hn1 = sigmoidf_(gs[3][1]) * tanhf(cn1);
            *reinterpret_cast<float2*>(c + (size_t)gb * HH + gj) = make_float2(cn0, cn1);
            *reinterpret_cast<float2*>(h + (size_t)gb * HH + gj) = make_float2(hn0, hn1);
            *reinterpret_cast<float2*>(act_out + ((size_t)gb * TT + t) * HH + gj) = make_float2(hn0, hn1);
        }

        grid_barrier();
    }
}

__global__ void copy_kernel(float* __restrict__ dst, const float* __restrict__ src, int n)
{
    int i = blockIdx.x * blockDim.x + threadIdx.x;
    if (i < n) dst[i] = src[i];
}

// ---------------- launch ----------------
extern "C" void kernel_launch(void* const* d_in, const int* in_sizes, int n_in,
                              void* d_out, int out_size)
{
    const float* x      = (const float*)d_in[0];   // [B,T,D]
    const float* hidden = (const float*)d_in[1];   // [L,B,H]
    const float* cell   = (const float*)d_in[2];   // [L,B,H]
    const float* W_ih   = (const float*)d_in[3];   // [L,4H,H]
    const float* W_hh   = (const float*)d_in[4];   // [L,4H,H]
    const float* bvec   = (const float*)d_in[5];   // [L,4H]
    const float* W_out  = (const float*)d_in[6];   // [D,H]
    const float* b_out  = (const float*)d_in[7];   // [D]
    float* out = (float*)d_out;

    float *p_gx, *p_act, *p_h, *p_c, *p_part;
    cudaGetSymbolAddress((void**)&p_gx,   g_gx);
    cudaGetSymbolAddress((void**)&p_act,  g_act);
    cudaGetSymbolAddress((void**)&p_h,    g_h);
    cudaGetSymbolAddress((void**)&p_c,    g_c);
    cudaGetSymbolAddress((void**)&p_part, g_part);

    float* acts[2] = { p_act, p_act + (size_t)BB * TT * HH };
    const float* lin = x;
    int sel = 0;

    const size_t LOGITS = (size_t)BB * TT * DD;
    const size_t STATE  = (size_t)BB * HH;
    const bool write_state = ((size_t)out_size >= LOGITS + 2 * LNUM * STATE);

    for (int l = 0; l < LNUM; l++) {
        copy_kernel<<<256, 256>>>(p_h, hidden + (size_t)l * STATE, (int)STATE);
        copy_kernel<<<256, 256>>>(p_c, cell   + (size_t)l * STATE, (int)STATE);

        // gx = act_in @ W_ih[l]^T + b[l]   (M=16384, N=4096, K=1024)
        gemm_nt<128, 128, 16, 16, 1><<<dim3(128, 32), 256>>>(
            lin, W_ih + (size_t)l * G4 * HH, bvec + (size_t)l * G4, p_gx, HH);

        // entire 256-step recurrence in one persistent kernel
        layer_recurrence<<<NBLK, 256>>>(
            p_gx, W_hh + (size_t)l * G4 * HH, p_h, p_c, p_part, acts[sel]);

        if (write_state) {
            copy_kernel<<<256, 256>>>(out + LOGITS + (size_t)l * STATE, p_h, (int)STATE);
            copy_kernel<<<256, 256>>>(out + LOGITS + LNUM * STATE + (size_t)l * STATE, p_c, (int)STATE);
        }
        lin = acts[sel];
        sel ^= 1;
    }

    // logits = act @ W_out^T + b_out  (M=16384, N=1024, K=1024)
    gemm_nt<128, 128, 16, 16, 0><<<dim3(128, 8), 256>>>(
        lin, W_out, b_out, out, HH);
}

// round 4
// speedup vs baseline: 1.2195x; 1.2195x over previous
#include <cuda_runtime.h>
#include <cuda_bf16.h>
#include <math.h>
#include <stdint.h>

// Problem constants
#define LNUM 4
#define BB   64
#define TT   256
#define HH   1024
#define DD   1024
#define G4   4096
#define NBLK 128

// ---------------- scratch (device globals; no runtime allocation) ----------------
__device__ float g_gx[(size_t)TT * BB * G4];
__device__ float g_act[2][(size_t)BB * TT * HH];
__device__ float g_h[BB * HH];
__device__ float g_c[BB * HH];
__device__ float g_part[(size_t)8 * BB * G4];
__device__ unsigned long long g_barctr;

// bf16 hi/lo split operands
__device__ __nv_bfloat16 g_ah[(size_t)BB * TT * HH];
__device__ __nv_bfloat16 g_al[(size_t)BB * TT * HH];
__device__ __nv_bfloat16 g_wih_h[(size_t)LNUM * G4 * HH];
__device__ __nv_bfloat16 g_wih_l[(size_t)LNUM * G4 * HH];
__device__ __nv_bfloat16 g_wout_h[(size_t)DD * HH];
__device__ __nv_bfloat16 g_wout_l[(size_t)DD * HH];

// ---------------- helpers ----------------
__device__ __forceinline__ uint32_t smem_u32(const void* p) {
    uint32_t a;
    asm("{ .reg .u64 t; cvta.to.shared.u64 t, %1; cvt.u32.u64 %0, t; }" : "=r"(a) : "l"(p));
    return a;
}
__device__ __forceinline__ unsigned long long pk2(float lo, float hi) {
    unsigned long long r;
    asm("mov.b64 %0, {%1, %2};" : "=l"(r) : "f"(lo), "f"(hi));
    return r;
}
__device__ __forceinline__ void upk2(unsigned long long v, float& lo, float& hi) {
    asm("mov.b64 {%0, %1}, %2;" : "=f"(lo), "=f"(hi) : "l"(v));
}
__device__ __forceinline__ void fma2(unsigned long long& acc, unsigned long long a, unsigned long long b) {
    asm("fma.rn.f32x2 %0, %1, %2, %0;" : "+l"(acc) : "l"(a), "l"(b));
}
__device__ __forceinline__ float sigmoidf_(float x) { return 1.0f / (1.0f + expf(-x)); }

// ---------------- grid barrier (monotonic ticket) ----------------
__device__ __forceinline__ void grid_barrier() {
    __syncthreads();
    if (threadIdx.x == 0) {
        __threadfence();
        unsigned long long ticket = atomicAdd(&g_barctr, 1ull);
        unsigned long long target = (ticket / NBLK + 1ull) * NBLK;
        while (*(volatile unsigned long long*)&g_barctr < target) __nanosleep(64);
        __threadfence();
    }
    __syncthreads();
}

// ---------------- fp32 -> bf16 hi/lo split ----------------
__global__ void __launch_bounds__(256)
split_kernel(const float* __restrict__ in, __nv_bfloat16* __restrict__ hi,
             __nv_bfloat16* __restrict__ lo, int n4)
{
    int i = blockIdx.x * blockDim.x + threadIdx.x;
    if (i >= n4) return;
    float4 v = reinterpret_cast<const float4*>(in)[i];
    __nv_bfloat16 h0 = __float2bfloat16(v.x), h1 = __float2bfloat16(v.y);
    __nv_bfloat16 h2 = __float2bfloat16(v.z), h3 = __float2bfloat16(v.w);
    __nv_bfloat16 l0 = __float2bfloat16(v.x - __bfloat162float(h0));
    __nv_bfloat16 l1 = __float2bfloat16(v.y - __bfloat162float(h1));
    __nv_bfloat16 l2 = __float2bfloat16(v.z - __bfloat162float(h2));
    __nv_bfloat16 l3 = __float2bfloat16(v.w - __bfloat162float(h3));
    __nv_bfloat162 hv0 = {h0, h1}, hv1 = {h2, h3};
    __nv_bfloat162 lv0 = {l0, l1}, lv1 = {l2, l3};
    reinterpret_cast<__nv_bfloat162*>(hi)[2 * i] = hv0;
    reinterpret_cast<__nv_bfloat162*>(hi)[2 * i + 1] = hv1;
    reinterpret_cast<__nv_bfloat162*>(lo)[2 * i] = lv0;
    reinterpret_cast<__nv_bfloat162*>(lo)[2 * i + 1] = lv1;
}

// ---------------- HMMA bf16-split GEMM ----------------
// C[m,n] = sum_k A[m,k]*B[n,k] + bias[n]  via  Ah*Bh + Al*Bh + Ah*Bl (fp32 acc)
// Block 128x128, 256 threads (8 warps, 4(m) x 2(n)), warp tile 32x64, BK=32.
// MODE 0: C row-major ldc = gridDim.y*128.  MODE 1: gx layout, m = b*TT+t -> row (t*BB+b), ldc=G4.
#define GK      1024
#define PITCH   40            // halves per SMEM row (80 B): conflict-free for ldmatrix
#define TILEH   (128 * PITCH) // halves per tile

__device__ __forceinline__ void ldm_x4(uint32_t& r0, uint32_t& r1, uint32_t& r2, uint32_t& r3, uint32_t addr) {
    asm volatile("ldmatrix.sync.aligned.m8n8.x4.shared.b16 {%0,%1,%2,%3}, [%4];"
                 : "=r"(r0), "=r"(r1), "=r"(r2), "=r"(r3) : "r"(addr));
}
__device__ __forceinline__ void mma16816(float* d, const uint32_t* a, uint32_t b0, uint32_t b1) {
    asm volatile("mma.sync.aligned.m16n8k16.row.col.f32.bf16.bf16.f32 "
                 "{%0,%1,%2,%3}, {%4,%5,%6,%7}, {%8,%9}, {%0,%1,%2,%3};"
                 : "+f"(d[0]), "+f"(d[1]), "+f"(d[2]), "+f"(d[3])
                 : "r"(a[0]), "r"(a[1]), "r"(a[2]), "r"(a[3]), "r"(b0), "r"(b1));
}
__device__ __forceinline__ void cp16(uint32_t saddr, const void* gaddr) {
    asm volatile("cp.async.cg.shared.global [%0], [%1], 16;" :: "r"(saddr), "l"(gaddr));
}

template<int MODE>
__global__ void __launch_bounds__(256, 1)
gemm_hmma(const __nv_bfloat16* __restrict__ Ah, const __nv_bfloat16* __restrict__ Al,
          const __nv_bfloat16* __restrict__ Bh, const __nv_bfloat16* __restrict__ Bl,
          const float* __restrict__ bias, float* __restrict__ C)
{
    __shared__ __align__(16) __nv_bfloat16 sA[2][TILEH];
    __shared__ __align__(16) __nv_bfloat16 sB[2][TILEH];

    const int tid = threadIdx.x;
    const int wid = tid >> 5;
    const int lid = tid & 31;
    const int m0 = blockIdx.x * 128;
    const int n0 = blockIdx.y * 128;
    const int warp_m = (wid >> 1) * 32;
    const int warp_n = (wid & 1) * 64;

    const uint32_t sAu = smem_u32(&sA[0][0]);
    const uint32_t sBu = smem_u32(&sB[0][0]);

    // preload helper: stage s, flat iter 'it' (phase = it/32, kb = (it%32)*32)
    auto preload = [&](int s, int it) {
        const int phase = it >> 5;
        const int kb = (it & 31) * 32;
        const __nv_bfloat16* Ap = (phase == 1) ? Al : Ah;
        const __nv_bfloat16* Bp = (phase == 2) ? Bl : Bh;
        const uint32_t sa = sAu + (uint32_t)s * TILEH * 2;
        const uint32_t sb = sBu + (uint32_t)s * TILEH * 2;
#pragma unroll
        for (int j = 0; j < 2; j++) {
            int c = tid + j * 256;               // 0..511
            int row = c >> 2, seg = c & 3;
            uint32_t so = (uint32_t)(row * 80 + seg * 16);
            cp16(sa + so, Ap + (size_t)(m0 + row) * GK + kb + seg * 8);
            cp16(sb + so, Bp + (size_t)(n0 + row) * GK + kb + seg * 8);
        }
        asm volatile("cp.async.commit_group;" ::: "memory");
    };

    // lane-dependent ldmatrix offsets
    const int q = lid >> 3, i8 = lid & 7;
    const int a_row = (q & 1) * 8 + i8;    // within m16
    const int a_k8  = (q >> 1) * 8;        // k half
    const int b_row = (q >> 1) * 8 + i8;   // within n16
    const int b_k8  = (q & 1) * 8;

    float acc[2][8][4];
#pragma unroll
    for (int mt = 0; mt < 2; mt++)
#pragma unroll
        for (int nt = 0; nt < 8; nt++)
#pragma unroll
            for (int e = 0; e < 4; e++) acc[mt][nt][e] = 0.0f;

    constexpr int NIT = 96;   // 3 phases * 32 kb
    preload(0, 0);

#pragma unroll 1
    for (int it = 0; it < NIT; it++) {
        const int s = it & 1;
        if (it + 1 < NIT) {
            preload(s ^ 1, it + 1);
            asm volatile("cp.async.wait_group 1;" ::: "memory");
        } else {
            asm volatile("cp.async.wait_group 0;" ::: "memory");
        }
        __syncthreads();

        const uint32_t sa = sAu + (uint32_t)s * TILEH * 2;
        const uint32_t sb = sBu + (uint32_t)s * TILEH * 2;
#pragma unroll
        for (int kk = 0; kk < 32; kk += 16) {
            uint32_t a[2][4], b[4][4];
#pragma unroll
            for (int mt = 0; mt < 2; mt++) {
                uint32_t addr = sa + (uint32_t)((warp_m + mt * 16 + a_row) * 80 + (kk + a_k8) * 2);
                ldm_x4(a[mt][0], a[mt][1], a[mt][2], a[mt][3], addr);
            }
#pragma unroll
            for (int ng = 0; ng < 4; ng++) {
                uint32_t addr = sb + (uint32_t)((warp_n + ng * 16 + b_row) * 80 + (kk + b_k8) * 2);
                ldm_x4(b[ng][0], b[ng][1], b[ng][2], b[ng][3], addr);
            }
#pragma unroll
            for (int mt = 0; mt < 2; mt++)
#pragma unroll
                for (int ng = 0; ng < 4; ng++) {
                    mma16816(acc[mt][2 * ng + 0], a[mt], b[ng][0], b[ng][1]);
                    mma16816(acc[mt][2 * ng + 1], a[mt], b[ng][2], b[ng][3]);
                }
        }
        __syncthreads();
    }

    // epilogue
    const int lr = lid >> 2;        // 0..7
    const int lc = (lid & 3) * 2;   // 0,2,4,6
#pragma unroll
    for (int mt = 0; mt < 2; mt++) {
#pragma unroll
        for (int rr = 0; rr < 2; rr++) {
            const int m = m0 + warp_m + mt * 16 + lr + rr * 8;
            size_t rowbase;
            if (MODE == 0) {
                const size_t ldc = (size_t)gridDim.y * 128;
                rowbase = (size_t)m * ldc + n0;
            } else {
                int t = m & (TT - 1), bb = m >> 8;
                rowbase = ((size_t)(t * BB + bb)) * G4 + n0;
            }
#pragma unroll
            for (int nt = 0; nt < 8; nt++) {
                const int n = warp_n + nt * 8 + lc;
                float2 v;
                v.x = acc[mt][nt][2 * rr + 0] + bias[n0 + n];
                v.y = acc[mt][nt][2 * rr + 1] + bias[n0 + n + 1];
                *reinterpret_cast<float2*>(C + rowbase + n) = v;
            }
        }
    }
}

// ---------------- persistent per-layer recurrence (fp32 FFMA2) ----------------
__global__ void __launch_bounds__(256, 1)
layer_recurrence(const float* __restrict__ gx, const float* __restrict__ Whh,
                 float* __restrict__ h, float* __restrict__ c,
                 float* __restrict__ part, float* __restrict__ act_out)
{
    __shared__ __align__(16) float As[16][64];
    __shared__ __align__(16) float Bs[16][256];

    const int tid = threadIdx.x;
    const int bid = blockIdx.x;
    const int tmi = tid >> 5;
    const int tni = tid & 31;
    const int n0 = (bid & 15) * 256;
    const int kz = bid >> 4;
    const int k0 = kz * 128;

    const int gbase = bid * 512 + tid * 2;
    const int gb = gbase >> 10;
    const int gj = gbase & 1023;

#pragma unroll 1
    for (int t = 0; t < TT; t++) {
        unsigned long long acc[4][8];
#pragma unroll
        for (int i = 0; i < 4; i++)
#pragma unroll
            for (int j = 0; j < 8; j++) acc[i][j] = 0ull;

#pragma unroll 1
        for (int kb = 0; kb < 128; kb += 16) {
            {
                int r = tid >> 2, c4 = (tid & 3) << 2;
                float4 v = __ldcg(reinterpret_cast<const float4*>(h + (size_t)r * HH + k0 + kb + c4));
                As[c4 + 0][r] = v.x; As[c4 + 1][r] = v.y; As[c4 + 2][r] = v.z; As[c4 + 3][r] = v.w;
            }
#pragma unroll
            for (int s = 0; s < 4; s++) {
                int ss = tid + s * 256;
                int r = ss >> 2, c4 = (ss & 3) << 2;
                float4 v = *reinterpret_cast<const float4*>(Whh + (size_t)(n0 + r) * HH + k0 + kb + c4);
                Bs[c4 + 0][r] = v.x; Bs[c4 + 1][r] = v.y; Bs[c4 + 2][r] = v.z; Bs[c4 + 3][r] = v.w;
            }
            __syncthreads();

#pragma unroll
            for (int kk = 0; kk < 16; kk++) {
                unsigned long long af[4], bsp[8];
#pragma unroll
                for (int i = 0; i < 4; i++)
                    af[i] = *reinterpret_cast<const unsigned long long*>(&As[kk][tmi * 8 + 2 * i]);
#pragma unroll
                for (int j = 0; j < 8; j++) {
                    float bv = Bs[kk][tni * 8 + j];
                    bsp[j] = pk2(bv, bv);
                }
#pragma unroll
                for (int i = 0; i < 4; i++)
#pragma unroll
                    for (int j = 0; j < 8; j++)
                        fma2(acc[i][j], af[i], bsp[j]);
            }
            __syncthreads();
        }

#pragma unroll
        for (int i = 0; i < 4; i++) {
            float lo[8], hi[8];
#pragma unroll
            for (int j = 0; j < 8; j++) upk2(acc[i][j], lo[j], hi[j]);
            int mA = tmi * 8 + 2 * i;
            size_t baseA = ((size_t)kz * BB + mA) * G4 + n0 + tni * 8;
            size_t baseB = baseA + G4;
            float4 a0 = {lo[0], lo[1], lo[2], lo[3]}, a1 = {lo[4], lo[5], lo[6], lo[7]};
            float4 b0 = {hi[0], hi[1], hi[2], hi[3]}, b1 = {hi[4], hi[5], hi[6], hi[7]};
            *reinterpret_cast<float4*>(part + baseA) = a0;
            *reinterpret_cast<float4*>(part + baseA + 4) = a1;
            *reinterpret_cast<float4*>(part + baseB) = b0;
            *reinterpret_cast<float4*>(part + baseB + 4) = b1;
        }

        grid_barrier();

        {
            const float* gxt = gx + (size_t)t * BB * G4;
            float gs[4][2];
#pragma unroll
            for (int q = 0; q < 4; q++) {
                size_t off = (size_t)gb * G4 + q * HH + gj;
                float2 s = *reinterpret_cast<const float2*>(gxt + off);
                gs[q][0] = s.x; gs[q][1] = s.y;
#pragma unroll
                for (int z = 0; z < 8; z++) {
                    float2 p = __ldcg(reinterpret_cast<const float2*>(
                        part + ((size_t)z * BB + gb) * G4 + q * HH + gj));
                    gs[q][0] += p.x; gs[q][1] += p.y;
                }
            }
            float2 cv = __ldcg(reinterpret_cast<const float2*>(c + (size_t)gb * HH + gj));
            float cn0 = sigmoidf_(gs[1][0]) * cv.x + sigmoidf_(gs[0][0]) * tanhf(gs[2][0]);
            float cn1 = sigmoidf_(gs[1][1]) * cv.y + sigmoidf_(gs[0][1]) * tanhf(gs[2][1]);
            float hn0 = sigmoidf_(gs[3][0]) * tanhf(cn0);
            float hn1 = sigmoidf_(gs[3][1]) * tanhf(cn1);
            *reinterpret_cast<float2*>(c + (size_t)gb * HH + gj) = make_float2(cn0, cn1);
            *reinterpret_cast<float2*>(h + (size_t)gb * HH + gj) = make_float2(hn0, hn1);
            *reinterpret_cast<float2*>(act_out + ((size_t)gb * TT + t) * HH + gj) = make_float2(hn0, hn1);
        }

        grid_barrier();
    }
}

__global__ void copy_kernel(float* __restrict__ dst, const float* __restrict__ src, int n)
{
    int i = blockIdx.x * blockDim.x + threadIdx.x;
    if (i < n) dst[i] = src[i];
}

// ---------------- launch ----------------
extern "C" void kernel_launch(void* const* d_in, const int* in_sizes, int n_in,
                              void* d_out, int out_size)
{
    const float* x      = (const float*)d_in[0];
    const float* hidden = (const float*)d_in[1];
    const float* cell   = (const float*)d_in[2];
    const float* W_ih   = (const float*)d_in[3];
    const float* W_hh   = (const float*)d_in[4];
    const float* bvec   = (const float*)d_in[5];
    const float* W_out  = (const float*)d_in[6];
    const float* b_out  = (const float*)d_in[7];
    float* out = (float*)d_out;

    float *p_gx, *p_act, *p_h, *p_c, *p_part;
    cudaGetSymbolAddress((void**)&p_gx,   g_gx);
    cudaGetSymbolAddress((void**)&p_act,  g_act);
    cudaGetSymbolAddress((void**)&p_h,    g_h);
    cudaGetSymbolAddress((void**)&p_c,    g_c);
    cudaGetSymbolAddress((void**)&p_part, g_part);
    __nv_bfloat16 *p_ah, *p_al, *p_wih_h, *p_wih_l, *p_wout_h, *p_wout_l;
    cudaGetSymbolAddress((void**)&p_ah, g_ah);
    cudaGetSymbolAddress((void**)&p_al, g_al);
    cudaGetSymbolAddress((void**)&p_wih_h, g_wih_h);
    cudaGetSymbolAddress((void**)&p_wih_l, g_wih_l);
    cudaGetSymbolAddress((void**)&p_wout_h, g_wout_h);
    cudaGetSymbolAddress((void**)&p_wout_l, g_wout_l);

    float* acts[2] = { p_act, p_act + (size_t)BB * TT * HH };
    const float* lin = x;
    int sel = 0;

    const size_t LOGITS = (size_t)BB * TT * DD;
    const size_t STATE  = (size_t)BB * HH;
    const bool write_state = ((size_t)out_size >= LOGITS + 2 * LNUM * STATE);

    // split weights once per launch
    {
        int n4 = (LNUM * G4 * HH) / 4;
        split_kernel<<<(n4 + 255) / 256, 256>>>(W_ih, p_wih_h, p_wih_l, n4);
        int m4 = (DD * HH) / 4;
        split_kernel<<<(m4 + 255) / 256, 256>>>(W_out, p_wout_h, p_wout_l, m4);
    }

    for (int l = 0; l < LNUM; l++) {
        copy_kernel<<<256, 256>>>(p_h, hidden + (size_t)l * STATE, (int)STATE);
        copy_kernel<<<256, 256>>>(p_c, cell   + (size_t)l * STATE, (int)STATE);

        // split layer input activations
        {
            int n4 = (BB * TT * HH) / 4;
            split_kernel<<<(n4 + 255) / 256, 256>>>(lin, p_ah, p_al, n4);
        }

        // gx = act_in @ W_ih[l]^T + b[l]  via HMMA bf16-split
        gemm_hmma<1><<<dim3(128, 32), 256>>>(
            p_ah, p_al,
            p_wih_h + (size_t)l * G4 * HH, p_wih_l + (size_t)l * G4 * HH,
            bvec + (size_t)l * G4, p_gx);

        layer_recurrence<<<NBLK, 256>>>(
            p_gx, W_hh + (size_t)l * G4 * HH, p_h, p_c, p_part, acts[sel]);

        if (write_state) {
            copy_kernel<<<256, 256>>>(out + LOGITS + (size_t)l * STATE, p_h, (int)STATE);
            copy_kernel<<<256, 256>>>(out + LOGITS + LNUM * STATE + (size_t)l * STATE, p_c, (int)STATE);
        }
        lin = acts[sel];
        sel ^= 1;
    }

    // logits = act @ W_out^T + b_out
    {
        int n4 = (BB * TT * HH) / 4;
        split_kernel<<<(n4 + 255) / 256, 256>>>(lin, p_ah, p_al, n4);
        gemm_hmma<0><<<dim3(128, 8), 256>>>(
            p_ah, p_al, p_wout_h, p_wout_l, b_out, out);
    }
}

// round 5
// speedup vs baseline: 2.1459x; 1.7596x over previous
#include <cuda_runtime.h>
#include <cuda_bf16.h>
#include <math.h>
#include <stdint.h>

// Problem constants
#define LNUM 4
#define BB   64
#define TT   256
#define HH   1024
#define DD   1024
#define G4   4096
#define NBLK 128

// ---------------- scratch (device globals) ----------------
__device__ float g_gx[(size_t)TT * BB * G4];               // [t][nt][b][32] block-local layout
__device__ unsigned long long g_barctr;

// bf16 hi/lo operands
__device__ __nv_bfloat16 g_acth[(size_t)BB * TT * HH];
__device__ __nv_bfloat16 g_actl[(size_t)BB * TT * HH];
__device__ __nv_bfloat16 g_hh[2][BB * HH];
__device__ __nv_bfloat16 g_hl[2][BB * HH];
__device__ __nv_bfloat16 g_wih_h[(size_t)LNUM * G4 * HH];
__device__ __nv_bfloat16 g_wih_l[(size_t)LNUM * G4 * HH];
__device__ __nv_bfloat16 g_whh_h[(size_t)LNUM * G4 * HH];
__device__ __nv_bfloat16 g_whh_l[(size_t)LNUM * G4 * HH];
__device__ __nv_bfloat16 g_wout_h[(size_t)DD * HH];
__device__ __nv_bfloat16 g_wout_l[(size_t)DD * HH];

// ---------------- helpers ----------------
__device__ __forceinline__ uint32_t smem_u32(const void* p) {
    uint32_t a;
    asm("{ .reg .u64 t; cvta.to.shared.u64 t, %1; cvt.u32.u64 %0, t; }" : "=r"(a) : "l"(p));
    return a;
}
__device__ __forceinline__ float sigmoidf_(float x) { return 1.0f / (1.0f + expf(-x)); }

__device__ __forceinline__ void ldm_x4(uint32_t& r0, uint32_t& r1, uint32_t& r2, uint32_t& r3, uint32_t addr) {
    asm volatile("ldmatrix.sync.aligned.m8n8.x4.shared.b16 {%0,%1,%2,%3}, [%4];"
                 : "=r"(r0), "=r"(r1), "=r"(r2), "=r"(r3) : "r"(addr));
}
__device__ __forceinline__ void mma16816(float* d, const uint32_t* a, uint32_t b0, uint32_t b1) {
    asm volatile("mma.sync.aligned.m16n8k16.row.col.f32.bf16.bf16.f32 "
                 "{%0,%1,%2,%3}, {%4,%5,%6,%7}, {%8,%9}, {%0,%1,%2,%3};"
                 : "+f"(d[0]), "+f"(d[1]), "+f"(d[2]), "+f"(d[3])
                 : "r"(a[0]), "r"(a[1]), "r"(a[2]), "r"(a[3]), "r"(b0), "r"(b1));
}
__device__ __forceinline__ void cp16(uint32_t saddr, const void* gaddr) {
    asm volatile("cp.async.cg.shared.global [%0], [%1], 16;" :: "r"(saddr), "l"(gaddr));
}

// ---------------- grid barrier (monotonic ticket) ----------------
__device__ __forceinline__ void grid_barrier() {
    __syncthreads();
    if (threadIdx.x == 0) {
        __threadfence();
        unsigned long long ticket = atomicAdd(&g_barctr, 1ull);
        unsigned long long target = (ticket / NBLK + 1ull) * NBLK;
        while (*(volatile unsigned long long*)&g_barctr < target) __nanosleep(32);
        __threadfence();
    }
    __syncthreads();
}

// ---------------- fp32 -> bf16 hi/lo split ----------------
__global__ void __launch_bounds__(256)
split_kernel(const float* __restrict__ in, __nv_bfloat16* __restrict__ hi,
             __nv_bfloat16* __restrict__ lo, int n4)
{
    int i = blockIdx.x * blockDim.x + threadIdx.x;
    if (i >= n4) return;
    float4 v = reinterpret_cast<const float4*>(in)[i];
    __nv_bfloat16 h0 = __float2bfloat16(v.x), h1 = __float2bfloat16(v.y);
    __nv_bfloat16 h2 = __float2bfloat16(v.z), h3 = __float2bfloat16(v.w);
    __nv_bfloat16 l0 = __float2bfloat16(v.x - __bfloat162float(h0));
    __nv_bfloat16 l1 = __float2bfloat16(v.y - __bfloat162float(h1));
    __nv_bfloat16 l2 = __float2bfloat16(v.z - __bfloat162float(h2));
    __nv_bfloat16 l3 = __float2bfloat16(v.w - __bfloat162float(h3));
    __nv_bfloat162 hv0 = {h0, h1}, hv1 = {h2, h3};
    __nv_bfloat162 lv0 = {l0, l1}, lv1 = {l2, l3};
    reinterpret_cast<__nv_bfloat162*>(hi)[2 * i] = hv0;
    reinterpret_cast<__nv_bfloat162*>(hi)[2 * i + 1] = hv1;
    reinterpret_cast<__nv_bfloat162*>(lo)[2 * i] = lv0;
    reinterpret_cast<__nv_bfloat162*>(lo)[2 * i + 1] = lv1;
}

// ---------------- HMMA bf16-split GEMM (gx + proj) ----------------
#define GK      1024
#define PITCH   40
#define TILEH   (128 * PITCH)

template<int MODE>
__global__ void __launch_bounds__(256, 1)
gemm_hmma(const __nv_bfloat16* __restrict__ Ah, const __nv_bfloat16* __restrict__ Al,
          const __nv_bfloat16* __restrict__ Bh, const __nv_bfloat16* __restrict__ Bl,
          const float* __restrict__ bias, float* __restrict__ C)
{
    __shared__ __align__(16) __nv_bfloat16 sA[2][TILEH];
    __shared__ __align__(16) __nv_bfloat16 sB[2][TILEH];

    const int tid = threadIdx.x;
    const int wid = tid >> 5;
    const int lid = tid & 31;
    const int m0 = blockIdx.x * 128;
    const int n0 = blockIdx.y * 128;
    const int warp_m = (wid >> 1) * 32;
    const int warp_n = (wid & 1) * 64;

    const uint32_t sAu = smem_u32(&sA[0][0]);
    const uint32_t sBu = smem_u32(&sB[0][0]);

    auto preload = [&](int s, int it) {
        const int phase = it >> 5;
        const int kb = (it & 31) * 32;
        const __nv_bfloat16* Ap = (phase == 1) ? Al : Ah;
        const __nv_bfloat16* Bp = (phase == 2) ? Bl : Bh;
        const uint32_t sa = sAu + (uint32_t)s * TILEH * 2;
        const uint32_t sb = sBu + (uint32_t)s * TILEH * 2;
#pragma unroll
        for (int j = 0; j < 2; j++) {
            int c = tid + j * 256;
            int row = c >> 2, seg = c & 3;
            uint32_t so = (uint32_t)(row * 80 + seg * 16);
            cp16(sa + so, Ap + (size_t)(m0 + row) * GK + kb + seg * 8);
            cp16(sb + so, Bp + (size_t)(n0 + row) * GK + kb + seg * 8);
        }
        asm volatile("cp.async.commit_group;" ::: "memory");
    };

    const int q = lid >> 3, i8 = lid & 7;
    const int a_row = (q & 1) * 8 + i8;
    const int a_k8  = (q >> 1) * 8;
    const int b_row = (q >> 1) * 8 + i8;
    const int b_k8  = (q & 1) * 8;

    float acc[2][8][4];
#pragma unroll
    for (int mt = 0; mt < 2; mt++)
#pragma unroll
        for (int nt = 0; nt < 8; nt++)
#pragma unroll
            for (int e = 0; e < 4; e++) acc[mt][nt][e] = 0.0f;

    constexpr int NIT = 96;
    preload(0, 0);

#pragma unroll 1
    for (int it = 0; it < NIT; it++) {
        const int s = it & 1;
        if (it + 1 < NIT) {
            preload(s ^ 1, it + 1);
            asm volatile("cp.async.wait_group 1;" ::: "memory");
        } else {
            asm volatile("cp.async.wait_group 0;" ::: "memory");
        }
        __syncthreads();

        const uint32_t sa = sAu + (uint32_t)s * TILEH * 2;
        const uint32_t sb = sBu + (uint32_t)s * TILEH * 2;
#pragma unroll
        for (int kk = 0; kk < 32; kk += 16) {
            uint32_t a[2][4], b[4][4];
#pragma unroll
            for (int mt = 0; mt < 2; mt++) {
                uint32_t addr = sa + (uint32_t)((warp_m + mt * 16 + a_row) * 80 + (kk + a_k8) * 2);
                ldm_x4(a[mt][0], a[mt][1], a[mt][2], a[mt][3], addr);
            }
#pragma unroll
            for (int ng = 0; ng < 4; ng++) {
                uint32_t addr = sb + (uint32_t)((warp_n + ng * 16 + b_row) * 80 + (kk + b_k8) * 2);
                ldm_x4(b[ng][0], b[ng][1], b[ng][2], b[ng][3], addr);
            }
#pragma unroll
            for (int mt = 0; mt < 2; mt++)
#pragma unroll
                for (int ng = 0; ng < 4; ng++) {
                    mma16816(acc[mt][2 * ng + 0], a[mt], b[ng][0], b[ng][1]);
                    mma16816(acc[mt][2 * ng + 1], a[mt], b[ng][2], b[ng][3]);
                }
        }
        __syncthreads();
    }

    const int lr = lid >> 2;
    const int lc = (lid & 3) * 2;
#pragma unroll
    for (int mt = 0; mt < 2; mt++) {
#pragma unroll
        for (int rr = 0; rr < 2; rr++) {
            const int m = m0 + warp_m + mt * 16 + lr + rr * 8;
#pragma unroll
            for (int nt = 0; nt < 8; nt++) {
                const int n = warp_n + nt * 8 + lc;
                float2 v;
                v.x = acc[mt][nt][2 * rr + 0] + bias[n0 + n];
                v.y = acc[mt][nt][2 * rr + 1] + bias[n0 + n + 1];
                size_t addr;
                if (MODE == 0) {
                    const size_t ldc = (size_t)gridDim.y * 128;
                    addr = (size_t)m * ldc + n0 + n;
                } else {
                    // gx block-local layout: [t][ntile][b][c], c = q*8 + (j&7)
                    int t = m & (TT - 1), bb = m >> 8;
                    int gcol = n0 + n;
                    int gq = gcol >> 10, gj = gcol & 1023;
                    addr = (((size_t)t * 128 + (gj >> 3)) * 64 + bb) * 32 + ((gq << 3) | (gj & 7));
                }
                *reinterpret_cast<float2*>(C + addr) = v;
            }
        }
    }
}

// ---------------- persistent recurrence: HMMA + smem-resident Whh ----------------
// 128 blocks x 256 threads. Block nt owns hidden cols [nt*8, nt*8+8) across all 4 gates
// (gate-cols c = q*8+jj -> global col q*1024 + nt*8 + jj). Full K=1024, no k-split.
// SMEM: Whh hi (64KB) | Whh lo (64KB) | h stream 2 stages x (hi 8KB + lo 8KB) | gbuf 8KB
#define S_WHH_H 0
#define S_WHH_L 65536
#define S_HSTR  131072
#define S_GBUF  163840
#define S_TOTAL 172032

__global__ void __launch_bounds__(256, 1)
lstm_rec(const float* __restrict__ gx,
         const __nv_bfloat16* __restrict__ WhhH, const __nv_bfloat16* __restrict__ WhhL,
         __nv_bfloat16* __restrict__ hh0, __nv_bfloat16* __restrict__ hl0,
         __nv_bfloat16* __restrict__ hh1, __nv_bfloat16* __restrict__ hl1,
         const float* __restrict__ cell_init,
         __nv_bfloat16* __restrict__ acth, __nv_bfloat16* __restrict__ actl,
         float* __restrict__ outh, float* __restrict__ outc, int do_state)
{
    extern __shared__ __align__(16) char smem[];
    const uint32_t sb = smem_u32(smem);
    const int tid = threadIdx.x;
    const int nt = blockIdx.x;
    const int wid = tid >> 5, lid = tid & 31;
    const int wm = wid >> 1, wn = wid & 1;     // 4(m) x 2(n) warps; warp tile 16x16

    // ---- load Whh slice (rows = gate-cols c of this block) into smem, swizzled ----
#pragma unroll 1
    for (int it = 0; it < 32; it++) {
        int s = it * 256 + tid;                 // 0..8191
        int type = s >> 12, idx = s & 4095;     // 32 rows x 128 segs
        int row = idx >> 7, gseg = idx & 127;
        int kt = gseg >> 3, seg = gseg & 7;
        int grow = (row >> 3) * 1024 + nt * 8 + (row & 7);
        const __nv_bfloat16* src = (type ? WhhL : WhhH) + (size_t)grow * 1024 + kt * 64 + seg * 8;
        uint32_t dst = sb + (type ? S_WHH_L : S_WHH_H) + kt * 4096
                     + ((row * 8 + (seg ^ (row & 7))) << 4);
        cp16(dst, src);
    }
    asm volatile("cp.async.commit_group;" ::: "memory");
    asm volatile("cp.async.wait_group 0;" ::: "memory");
    __syncthreads();

    // lane fragment offsets (same scheme as gemm_hmma)
    const int q = lid >> 3, i8 = lid & 7;
    const int a_row = (q & 1) * 8 + i8, a_k8 = (q >> 1) * 8;
    const int b_row = (q >> 1) * 8 + i8, b_k8 = (q & 1) * 8;

    // gates-phase element assignment: 2 consecutive j's
    const int e0 = tid * 2;
    const int gb = e0 >> 3;          // batch 0..63
    const int gj = e0 & 7;           // 0,2,4,6
    float cst0 = cell_init[gb * HH + nt * 8 + gj];
    float cst1 = cell_init[gb * HH + nt * 8 + gj + 1];

    float* gbuf = reinterpret_cast<float*>(smem + S_GBUF);

#pragma unroll 1
    for (int t = 0; t < TT; t++) {
        const __nv_bfloat16* hhr = (t & 1) ? hh1 : hh0;
        const __nv_bfloat16* hlr = (t & 1) ? hl1 : hl0;
        __nv_bfloat16* hhw = (t & 1) ? hh0 : hh1;
        __nv_bfloat16* hlw = (t & 1) ? hl0 : hl1;

        auto load_chunk = [&](int kt, int stage) {
#pragma unroll
            for (int j2 = 0; j2 < 4; j2++) {
                int c = tid + j2 * 256;              // 0..1023
                int type = c >> 9, idx = c & 511;    // 64 rows x 8 segs
                int row = idx >> 3, seg = idx & 7;
                const __nv_bfloat16* src = (type ? hlr : hhr) + (size_t)row * HH + kt * 64 + seg * 8;
                uint32_t dst = sb + S_HSTR + stage * 16384 + type * 8192
                             + ((row * 8 + (seg ^ (row & 7))) << 4);
                cp16(dst, src);
            }
            asm volatile("cp.async.commit_group;" ::: "memory");
        };

        float acc[2][4];
#pragma unroll
        for (int n8 = 0; n8 < 2; n8++)
#pragma unroll
            for (int e = 0; e < 4; e++) acc[n8][e] = 0.0f;

        load_chunk(0, 0);
#pragma unroll 1
        for (int kt = 0; kt < 16; kt++) {
            const int stage = kt & 1;
            if (kt < 15) {
                load_chunk(kt + 1, stage ^ 1);
                asm volatile("cp.async.wait_group 1;" ::: "memory");
            } else {
                asm volatile("cp.async.wait_group 0;" ::: "memory");
            }
            __syncthreads();

            const uint32_t ha = sb + S_HSTR + stage * 16384;
            const uint32_t wt = sb + kt * 4096;
#pragma unroll
            for (int kk = 0; kk < 64; kk += 16) {
                uint32_t ah[4], al[4], wh[4], wl[4];
                {
                    int row = wm * 16 + a_row, seg = (kk + a_k8) >> 3;
                    uint32_t off = (uint32_t)((row * 8 + (seg ^ (row & 7))) << 4);
                    ldm_x4(ah[0], ah[1], ah[2], ah[3], ha + off);
                    ldm_x4(al[0], al[1], al[2], al[3], ha + 8192 + off);
                }
                {
                    int row = wn * 16 + b_row, seg = (kk + b_k8) >> 3;
                    uint32_t off = (uint32_t)((row * 8 + (seg ^ (row & 7))) << 4);
                    ldm_x4(wh[0], wh[1], wh[2], wh[3], wt + S_WHH_H + off);
                    ldm_x4(wl[0], wl[1], wl[2], wl[3], wt + S_WHH_L + off);
                }
                mma16816(acc[0], ah, wh[0], wh[1]);
                mma16816(acc[1], ah, wh[2], wh[3]);
                mma16816(acc[0], al, wh[0], wh[1]);
                mma16816(acc[1], al, wh[2], wh[3]);
                mma16816(acc[0], ah, wl[0], wl[1]);
                mma16816(acc[1], ah, wl[2], wl[3]);
            }
            __syncthreads();
        }

        // stage acc -> gbuf[64][32]
        {
            const int lr = lid >> 2, lc = (lid & 3) * 2;
            const int r0 = wm * 16 + lr;
#pragma unroll
            for (int n8 = 0; n8 < 2; n8++) {
                const int col = wn * 16 + n8 * 8 + lc;
                *reinterpret_cast<float2*>(&gbuf[r0 * 32 + col]) = make_float2(acc[n8][0], acc[n8][1]);
                *reinterpret_cast<float2*>(&gbuf[(r0 + 8) * 32 + col]) = make_float2(acc[n8][2], acc[n8][3]);
            }
        }
        __syncthreads();

        // gates for (gb, gj), (gb, gj+1)
        {
            const float* gxt = gx + (((size_t)t * 128 + nt) * 64 + gb) * 32;
            float2 xi = *reinterpret_cast<const float2*>(gxt + gj);
            float2 xf = *reinterpret_cast<const float2*>(gxt + 8 + gj);
            float2 xg = *reinterpret_cast<const float2*>(gxt + 16 + gj);
            float2 xo = *reinterpret_cast<const float2*>(gxt + 24 + gj);
            float gi0 = gbuf[gb * 32 + gj]      + xi.x, gi1 = gbuf[gb * 32 + gj + 1]      + xi.y;
            float gf0 = gbuf[gb * 32 + 8 + gj]  + xf.x, gf1 = gbuf[gb * 32 + 8 + gj + 1]  + xf.y;
            float gg0 = gbuf[gb * 32 + 16 + gj] + xg.x, gg1 = gbuf[gb * 32 + 16 + gj + 1] + xg.y;
            float go0 = gbuf[gb * 32 + 24 + gj] + xo.x, go1 = gbuf[gb * 32 + 24 + gj + 1] + xo.y;

            cst0 = sigmoidf_(gf0) * cst0 + sigmoidf_(gi0) * tanhf(gg0);
            cst1 = sigmoidf_(gf1) * cst1 + sigmoidf_(gi1) * tanhf(gg1);
            float h0 = sigmoidf_(go0) * tanhf(cst0);
            float h1 = sigmoidf_(go1) * tanhf(cst1);

            __nv_bfloat16 bh0 = __float2bfloat16(h0), bh1 = __float2bfloat16(h1);
            __nv_bfloat16 bl0 = __float2bfloat16(h0 - __bfloat162float(bh0));
            __nv_bfloat16 bl1 = __float2bfloat16(h1 - __bfloat162float(bh1));
            __nv_bfloat162 bhv = {bh0, bh1}, blv = {bl0, bl1};

            const int hidx = gb * HH + nt * 8 + gj;
            *reinterpret_cast<__nv_bfloat162*>(hhw + hidx) = bhv;
            *reinterpret_cast<__nv_bfloat162*>(hlw + hidx) = blv;
            const size_t aidx = ((size_t)gb * TT + t) * HH + nt * 8 + gj;
            *reinterpret_cast<__nv_bfloat162*>(acth + aidx) = bhv;
            *reinterpret_cast<__nv_bfloat162*>(actl + aidx) = blv;
            if (do_state && t == TT - 1) {
                *reinterpret_cast<float2*>(outh + hidx) = make_float2(h0, h1);
                *reinterpret_cast<float2*>(outc + hidx) = make_float2(cst0, cst1);
            }
        }

        grid_barrier();
    }
}

// ---------------- launch ----------------
extern "C" void kernel_launch(void* const* d_in, const int* in_sizes, int n_in,
                              void* d_out, int out_size)
{
    const float* x      = (const float*)d_in[0];
    const float* hidden = (const float*)d_in[1];
    const float* cell   = (const float*)d_in[2];
    const float* W_ih   = (const float*)d_in[3];
    const float* W_hh   = (const float*)d_in[4];
    const float* bvec   = (const float*)d_in[5];
    const float* W_out  = (const float*)d_in[6];
    const float* b_out  = (const float*)d_in[7];
    float* out = (float*)d_out;

    float* p_gx;
    cudaGetSymbolAddress((void**)&p_gx, g_gx);
    __nv_bfloat16 *p_acth, *p_actl, *p_hh, *p_hl;
    __nv_bfloat16 *p_wih_h, *p_wih_l, *p_whh_h, *p_whh_l, *p_wout_h, *p_wout_l;
    cudaGetSymbolAddress((void**)&p_acth, g_acth);
    cudaGetSymbolAddress((void**)&p_actl, g_actl);
    cudaGetSymbolAddress((void**)&p_hh, g_hh);
    cudaGetSymbolAddress((void**)&p_hl, g_hl);
    cudaGetSymbolAddress((void**)&p_wih_h, g_wih_h);
    cudaGetSymbolAddress((void**)&p_wih_l, g_wih_l);
    cudaGetSymbolAddress((void**)&p_whh_h, g_whh_h);
    cudaGetSymbolAddress((void**)&p_whh_l, g_whh_l);
    cudaGetSymbolAddress((void**)&p_wout_h, g_wout_h);
    cudaGetSymbolAddress((void**)&p_wout_l, g_wout_l);

    cudaFuncSetAttribute(lstm_rec, cudaFuncAttributeMaxDynamicSharedMemorySize, S_TOTAL);

    const size_t LOGITS = (size_t)BB * TT * DD;
    const size_t STATE  = (size_t)BB * HH;
    const int write_state = ((size_t)out_size >= LOGITS + 2 * LNUM * STATE) ? 1 : 0;

    // one-time-per-launch weight splits
    {
        int n4 = (LNUM * G4 * HH) / 4;
        split_kernel<<<(n4 + 255) / 256, 256>>>(W_ih, p_wih_h, p_wih_l, n4);
        split_kernel<<<(n4 + 255) / 256, 256>>>(W_hh, p_whh_h, p_whh_l, n4);
        int m4 = (DD * HH) / 4;
        split_kernel<<<(m4 + 255) / 256, 256>>>(W_out, p_wout_h, p_wout_l, m4);
    }
    // first-layer activations = x split
    {
        int n4 = (BB * TT * HH) / 4;
        split_kernel<<<(n4 + 255) / 256, 256>>>(x, p_acth, p_actl, n4);
    }

    for (int l = 0; l < LNUM; l++) {
        // gx = act @ W_ih[l]^T + b[l]  (writes block-local layout)
        gemm_hmma<1><<<dim3(128, 32), 256>>>(
            p_acth, p_actl,
            p_wih_h + (size_t)l * G4 * HH, p_wih_l + (size_t)l * G4 * HH,
            bvec + (size_t)l * G4, p_gx);

        // h0 split into parity-0 buffers
        {
            int n4 = (int)(STATE / 4);
            split_kernel<<<(n4 + 255) / 256, 256>>>(hidden + (size_t)l * STATE, p_hh, p_hl, n4);
        }

        lstm_rec<<<NBLK, 256, S_TOTAL>>>(
            p_gx,
            p_whh_h + (size_t)l * G4 * HH, p_whh_l + (size_t)l * G4 * HH,
            p_hh, p_hl, p_hh + STATE, p_hl + STATE,
            cell + (size_t)l * STATE,
            p_acth, p_actl,
            out + LOGITS + (size_t)l * STATE,
            out + LOGITS + LNUM * STATE + (size_t)l * STATE,
            write_state);
    }

    // logits = act @ W_out^T + b_out
    gemm_hmma<0><<<dim3(128, 8), 256>>>(
        p_acth, p_actl, p_wout_h, p_wout_l, b_out, out);
}

// round 6
// speedup vs baseline: 2.1945x; 1.0227x over previous
#include <cuda_runtime.h>
#include <cuda_bf16.h>
#include <math.h>
#include <stdint.h>

// Problem constants
#define LNUM 4
#define BB   64
#define TT   256
#define HH   1024
#define DD   1024
#define G4   4096
#define NBLK 128

// ---------------- scratch (device globals) ----------------
__device__ float g_gx[(size_t)TT * BB * G4];               // [t][nt][b][32] block-local layout
__device__ unsigned long long g_barctr;

__device__ __nv_bfloat16 g_acth[(size_t)BB * TT * HH];
__device__ __nv_bfloat16 g_actl[(size_t)BB * TT * HH];
__device__ __nv_bfloat16 g_hh[2][BB * HH];
__device__ __nv_bfloat16 g_hl[2][BB * HH];
__device__ __nv_bfloat16 g_wih_h[(size_t)LNUM * G4 * HH];
__device__ __nv_bfloat16 g_wih_l[(size_t)LNUM * G4 * HH];
__device__ __nv_bfloat16 g_whh_h[(size_t)LNUM * G4 * HH];
__device__ __nv_bfloat16 g_whh_l[(size_t)LNUM * G4 * HH];
__device__ __nv_bfloat16 g_wout_h[(size_t)DD * HH];
__device__ __nv_bfloat16 g_wout_l[(size_t)DD * HH];

// ---------------- helpers ----------------
__device__ __forceinline__ uint32_t smem_u32(const void* p) {
    uint32_t a;
    asm("{ .reg .u64 t; cvta.to.shared.u64 t, %1; cvt.u32.u64 %0, t; }" : "=r"(a) : "l"(p));
    return a;
}
__device__ __forceinline__ float sigmoidf_(float x) { return 1.0f / (1.0f + expf(-x)); }

__device__ __forceinline__ void ldm_x4(uint32_t& r0, uint32_t& r1, uint32_t& r2, uint32_t& r3, uint32_t addr) {
    asm volatile("ldmatrix.sync.aligned.m8n8.x4.shared.b16 {%0,%1,%2,%3}, [%4];"
                 : "=r"(r0), "=r"(r1), "=r"(r2), "=r"(r3) : "r"(addr));
}
__device__ __forceinline__ void mma16816(float* d, const uint32_t* a, uint32_t b0, uint32_t b1) {
    asm volatile("mma.sync.aligned.m16n8k16.row.col.f32.bf16.bf16.f32 "
                 "{%0,%1,%2,%3}, {%4,%5,%6,%7}, {%8,%9}, {%0,%1,%2,%3};"
                 : "+f"(d[0]), "+f"(d[1]), "+f"(d[2]), "+f"(d[3])
                 : "r"(a[0]), "r"(a[1]), "r"(a[2]), "r"(a[3]), "r"(b0), "r"(b1));
}
__device__ __forceinline__ void cp16(uint32_t saddr, const void* gaddr) {
    asm volatile("cp.async.cg.shared.global [%0], [%1], 16;" :: "r"(saddr), "l"(gaddr));
}

// ---------------- grid barrier (monotonic ticket) ----------------
__device__ __forceinline__ void grid_barrier() {
    __syncthreads();
    if (threadIdx.x == 0) {
        __threadfence();
        unsigned long long ticket = atomicAdd(&g_barctr, 1ull);
        unsigned long long target = (ticket / NBLK + 1ull) * NBLK;
        while (*(volatile unsigned long long*)&g_barctr < target) __nanosleep(32);
        __threadfence();
    }
    __syncthreads();
}

// ---------------- fp32 -> bf16 hi/lo split ----------------
__global__ void __launch_bounds__(256)
split_kernel(const float* __restrict__ in, __nv_bfloat16* __restrict__ hi,
             __nv_bfloat16* __restrict__ lo, int n4)
{
    int i = blockIdx.x * blockDim.x + threadIdx.x;
    if (i >= n4) return;
    float4 v = reinterpret_cast<const float4*>(in)[i];
    __nv_bfloat16 h0 = __float2bfloat16(v.x), h1 = __float2bfloat16(v.y);
    __nv_bfloat16 h2 = __float2bfloat16(v.z), h3 = __float2bfloat16(v.w);
    __nv_bfloat16 l0 = __float2bfloat16(v.x - __bfloat162float(h0));
    __nv_bfloat16 l1 = __float2bfloat16(v.y - __bfloat162float(h1));
    __nv_bfloat16 l2 = __float2bfloat16(v.z - __bfloat162float(h2));
    __nv_bfloat16 l3 = __float2bfloat16(v.w - __bfloat162float(h3));
    __nv_bfloat162 hv0 = {h0, h1}, hv1 = {h2, h3};
    __nv_bfloat162 lv0 = {l0, l1}, lv1 = {l2, l3};
    reinterpret_cast<__nv_bfloat162*>(hi)[2 * i] = hv0;
    reinterpret_cast<__nv_bfloat162*>(hi)[2 * i + 1] = hv1;
    reinterpret_cast<__nv_bfloat162*>(lo)[2 * i] = lv0;
    reinterpret_cast<__nv_bfloat162*>(lo)[2 * i + 1] = lv1;
}

// ---------------- HMMA bf16-split GEMM (gx + proj), unchanged from R5 ----------------
#define GK      1024
#define PITCH   40
#define TILEH   (128 * PITCH)

template<int MODE>
__global__ void __launch_bounds__(256, 1)
gemm_hmma(const __nv_bfloat16* __restrict__ Ah, const __nv_bfloat16* __restrict__ Al,
          const __nv_bfloat16* __restrict__ Bh, const __nv_bfloat16* __restrict__ Bl,
          const float* __restrict__ bias, float* __restrict__ C)
{
    __shared__ __align__(16) __nv_bfloat16 sA[2][TILEH];
    __shared__ __align__(16) __nv_bfloat16 sB[2][TILEH];

    const int tid = threadIdx.x;
    const int wid = tid >> 5;
    const int lid = tid & 31;
    const int m0 = blockIdx.x * 128;
    const int n0 = blockIdx.y * 128;
    const int warp_m = (wid >> 1) * 32;
    const int warp_n = (wid & 1) * 64;

    const uint32_t sAu = smem_u32(&sA[0][0]);
    const uint32_t sBu = smem_u32(&sB[0][0]);

    auto preload = [&](int s, int it) {
        const int phase = it >> 5;
        const int kb = (it & 31) * 32;
        const __nv_bfloat16* Ap = (phase == 1) ? Al : Ah;
        const __nv_bfloat16* Bp = (phase == 2) ? Bl : Bh;
        const uint32_t sa = sAu + (uint32_t)s * TILEH * 2;
        const uint32_t sb = sBu + (uint32_t)s * TILEH * 2;
#pragma unroll
        for (int j = 0; j < 2; j++) {
            int c = tid + j * 256;
            int row = c >> 2, seg = c & 3;
            uint32_t so = (uint32_t)(row * 80 + seg * 16);
            cp16(sa + so, Ap + (size_t)(m0 + row) * GK + kb + seg * 8);
            cp16(sb + so, Bp + (size_t)(n0 + row) * GK + kb + seg * 8);
        }
        asm volatile("cp.async.commit_group;" ::: "memory");
    };

    const int q = lid >> 3, i8 = lid & 7;
    const int a_row = (q & 1) * 8 + i8;
    const int a_k8  = (q >> 1) * 8;
    const int b_row = (q >> 1) * 8 + i8;
    const int b_k8  = (q & 1) * 8;

    float acc[2][8][4];
#pragma unroll
    for (int mt = 0; mt < 2; mt++)
#pragma unroll
        for (int nt = 0; nt < 8; nt++)
#pragma unroll
            for (int e = 0; e < 4; e++) acc[mt][nt][e] = 0.0f;

    constexpr int NIT = 96;
    preload(0, 0);

#pragma unroll 1
    for (int it = 0; it < NIT; it++) {
        const int s = it & 1;
        if (it + 1 < NIT) {
            preload(s ^ 1, it + 1);
            asm volatile("cp.async.wait_group 1;" ::: "memory");
        } else {
            asm volatile("cp.async.wait_group 0;" ::: "memory");
        }
        __syncthreads();

        const uint32_t sa = sAu + (uint32_t)s * TILEH * 2;
        const uint32_t sb = sBu + (uint32_t)s * TILEH * 2;
#pragma unroll
        for (int kk = 0; kk < 32; kk += 16) {
            uint32_t a[2][4], b[4][4];
#pragma unroll
            for (int mt = 0; mt < 2; mt++) {
                uint32_t addr = sa + (uint32_t)((warp_m + mt * 16 + a_row) * 80 + (kk + a_k8) * 2);
                ldm_x4(a[mt][0], a[mt][1], a[mt][2], a[mt][3], addr);
            }
#pragma unroll
            for (int ng = 0; ng < 4; ng++) {
                uint32_t addr = sb + (uint32_t)((warp_n + ng * 16 + b_row) * 80 + (kk + b_k8) * 2);
                ldm_x4(b[ng][0], b[ng][1], b[ng][2], b[ng][3], addr);
            }
#pragma unroll
            for (int mt = 0; mt < 2; mt++)
#pragma unroll
                for (int ng = 0; ng < 4; ng++) {
                    mma16816(acc[mt][2 * ng + 0], a[mt], b[ng][0], b[ng][1]);
                    mma16816(acc[mt][2 * ng + 1], a[mt], b[ng][2], b[ng][3]);
                }
        }
        __syncthreads();
    }

    const int lr = lid >> 2;
    const int lc = (lid & 3) * 2;
#pragma unroll
    for (int mt = 0; mt < 2; mt++) {
#pragma unroll
        for (int rr = 0; rr < 2; rr++) {
            const int m = m0 + warp_m + mt * 16 + lr + rr * 8;
#pragma unroll
            for (int nt = 0; nt < 8; nt++) {
                const int n = warp_n + nt * 8 + lc;
                float2 v;
                v.x = acc[mt][nt][2 * rr + 0] + bias[n0 + n];
                v.y = acc[mt][nt][2 * rr + 1] + bias[n0 + n + 1];
                size_t addr;
                if (MODE == 0) {
                    const size_t ldc = (size_t)gridDim.y * 128;
                    addr = (size_t)m * ldc + n0 + n;
                } else {
                    int t = m & (TT - 1), bb = m >> 8;
                    int gcol = n0 + n;
                    int gq = gcol >> 10, gj = gcol & 1023;
                    addr = (((size_t)t * 128 + (gj >> 3)) * 64 + bb) * 32 + ((gq << 3) | (gj & 7));
                }
                *reinterpret_cast<float2*>(C + addr) = v;
            }
        }
    }
}

// ---------------- persistent recurrence v2: phase-split accumulators, 128-col chunks ----------------
// SMEM: Whh hi 64KB | Whh lo 64KB | h stream 2 stages x 32KB | gbuf 8KB  = 200KB
#define S_WHH_H 0
#define S_WHH_L 65536
#define S_HSTR  131072
#define S_GBUF  196608
#define S_TOTAL 204800

__global__ void __launch_bounds__(256, 1)
lstm_rec(const float* __restrict__ gx,
         const __nv_bfloat16* __restrict__ WhhH, const __nv_bfloat16* __restrict__ WhhL,
         __nv_bfloat16* __restrict__ hh0, __nv_bfloat16* __restrict__ hl0,
         __nv_bfloat16* __restrict__ hh1, __nv_bfloat16* __restrict__ hl1,
         const float* __restrict__ cell_init,
         __nv_bfloat16* __restrict__ acth, __nv_bfloat16* __restrict__ actl,
         float* __restrict__ outh, float* __restrict__ outc, int do_state)
{
    extern __shared__ __align__(16) char smem[];
    const uint32_t sb = smem_u32(smem);
    const int tid = threadIdx.x;
    const int nt = blockIdx.x;
    const int wid = tid >> 5, lid = tid & 31;
    const int wm = wid >> 1, wn = wid & 1;     // 4(m) x 2(n); warp tile 16x16

    // ---- Whh slice into smem: row = gate-col (0..31), flat k (0..1023), swizzled ----
#pragma unroll 1
    for (int it = 0; it < 32; it++) {
        int s = it * 256 + tid;                 // 0..8191
        int type = s >> 12, idx = s & 4095;     // 32 rows x 128 segs
        int row = idx >> 7, seg = idx & 127;
        int grow = (row >> 3) * 1024 + nt * 8 + (row & 7);
        const __nv_bfloat16* src = (type ? WhhL : WhhH) + (size_t)grow * 1024 + seg * 8;
        uint32_t dst = sb + (type ? S_WHH_L : S_WHH_H)
                     + (uint32_t)(row * 2048 + ((seg ^ (row & 7)) << 4));
        cp16(dst, src);
    }
    asm volatile("cp.async.commit_group;" ::: "memory");
    asm volatile("cp.async.wait_group 0;" ::: "memory");
    __syncthreads();

    const int q = lid >> 3, i8 = lid & 7;
    const int a_row = (q & 1) * 8 + i8, a_k8 = (q >> 1) * 8;
    const int b_row = (q >> 1) * 8 + i8, b_k8 = (q & 1) * 8;

    const int e0 = tid * 2;
    const int gb = e0 >> 3;          // batch 0..63
    const int gj = e0 & 7;           // 0,2,4,6
    float cst0 = cell_init[gb * HH + nt * 8 + gj];
    float cst1 = cell_init[gb * HH + nt * 8 + gj + 1];

    float* gbuf = reinterpret_cast<float*>(smem + S_GBUF);

    // precomputed warp fragment smem offsets
    const int arow_full = wm * 16 + a_row;                 // 0..63
    const uint32_t a_base = (uint32_t)(arow_full * 256);
    const int wrow = wn * 16 + b_row;                      // 0..31
    const uint32_t w_base = (uint32_t)(wrow * 2048);
    const int arow7 = arow_full & 7, wrow7 = wrow & 7;

#pragma unroll 1
    for (int t = 0; t < TT; t++) {
        const __nv_bfloat16* hhr = (t & 1) ? hh1 : hh0;
        const __nv_bfloat16* hlr = (t & 1) ? hl1 : hl0;
        __nv_bfloat16* hhw = (t & 1) ? hh0 : hh1;
        __nv_bfloat16* hlw = (t & 1) ? hl0 : hl1;

        auto load_chunk = [&](int ck, int stage) {
#pragma unroll
            for (int j2 = 0; j2 < 8; j2++) {
                int c = tid + j2 * 256;                 // 0..2047
                int type = c >> 10, idx = c & 1023;     // 64 rows x 16 segs
                int row = idx >> 4, seg = idx & 15;
                const __nv_bfloat16* src = (type ? hlr : hhr) + (size_t)row * HH + ck * 128 + seg * 8;
                uint32_t dst = sb + S_HSTR + stage * 32768 + type * 16384
                             + (uint32_t)(row * 256 + ((seg ^ (row & 7)) << 4));
                cp16(dst, src);
            }
            asm volatile("cp.async.commit_group;" ::: "memory");
        };

        // phase-split accumulators: 6 independent HMMA chains per warp
        float acc[3][2][4];
#pragma unroll
        for (int p = 0; p < 3; p++)
#pragma unroll
            for (int n8 = 0; n8 < 2; n8++)
#pragma unroll
                for (int e = 0; e < 4; e++) acc[p][n8][e] = 0.0f;

        load_chunk(0, 0);
#pragma unroll 1
        for (int ck = 0; ck < 8; ck++) {
            const int stage = ck & 1;
            if (ck < 7) {
                load_chunk(ck + 1, stage ^ 1);
                asm volatile("cp.async.wait_group 1;" ::: "memory");
            } else {
                asm volatile("cp.async.wait_group 0;" ::: "memory");
            }
            __syncthreads();

            const uint32_t ha = sb + S_HSTR + stage * 32768;
#pragma unroll
            for (int kk = 0; kk < 128; kk += 16) {
                uint32_t ah[4], al[4], wh[4], wl[4];
                {
                    int seg = (kk + a_k8) >> 3;
                    uint32_t off = a_base + ((uint32_t)(seg ^ arow7) << 4);
                    ldm_x4(ah[0], ah[1], ah[2], ah[3], ha + off);
                    ldm_x4(al[0], al[1], al[2], al[3], ha + 16384 + off);
                }
                {
                    int wseg = (ck * 128 + kk + b_k8) >> 3;
                    uint32_t off = w_base + ((uint32_t)(wseg ^ wrow7) << 4);
                    ldm_x4(wh[0], wh[1], wh[2], wh[3], sb + S_WHH_H + off);
                    ldm_x4(wl[0], wl[1], wl[2], wl[3], sb + S_WHH_L + off);
                }
                mma16816(acc[0][0], ah, wh[0], wh[1]);
                mma16816(acc[0][1], ah, wh[2], wh[3]);
                mma16816(acc[1][0], al, wh[0], wh[1]);
                mma16816(acc[1][1], al, wh[2], wh[3]);
                mma16816(acc[2][0], ah, wl[0], wl[1]);
                mma16816(acc[2][1], ah, wl[2], wl[3]);
            }
            __syncthreads();
        }

        // stage summed acc -> gbuf[64][32]
        {
            const int lr = lid >> 2, lc = (lid & 3) * 2;
            const int r0 = wm * 16 + lr;
#pragma unroll
            for (int n8 = 0; n8 < 2; n8++) {
                const int col = wn * 16 + n8 * 8 + lc;
                float s0 = acc[0][n8][0] + acc[1][n8][0] + acc[2][n8][0];
                float s1 = acc[0][n8][1] + acc[1][n8][1] + acc[2][n8][1];
                float s2 = acc[0][n8][2] + acc[1][n8][2] + acc[2][n8][2];
                float s3 = acc[0][n8][3] + acc[1][n8][3] + acc[2][n8][3];
                *reinterpret_cast<float2*>(&gbuf[r0 * 32 + col]) = make_float2(s0, s1);
                *reinterpret_cast<float2*>(&gbuf[(r0 + 8) * 32 + col]) = make_float2(s2, s3);
            }
        }
        __syncthreads();

        // gates
        {
            const float* gxt = gx + (((size_t)t * 128 + nt) * 64 + gb) * 32;
            float2 xi = *reinterpret_cast<const float2*>(gxt + gj);
            float2 xf = *reinterpret_cast<const float2*>(gxt + 8 + gj);
            float2 xg = *reinterpret_cast<const float2*>(gxt + 16 + gj);
            float2 xo = *reinterpret_cast<const float2*>(gxt + 24 + gj);
            float gi0 = gbuf[gb * 32 + gj]      + xi.x, gi1 = gbuf[gb * 32 + gj + 1]      + xi.y;
            float gf0 = gbuf[gb * 32 + 8 + gj]  + xf.x, gf1 = gbuf[gb * 32 + 8 + gj + 1]  + xf.y;
            float gg0 = gbuf[gb * 32 + 16 + gj] + xg.x, gg1 = gbuf[gb * 32 + 16 + gj + 1] + xg.y;
            float go0 = gbuf[gb * 32 + 24 + gj] + xo.x, go1 = gbuf[gb * 32 + 24 + gj + 1] + xo.y;

            cst0 = sigmoidf_(gf0) * cst0 + sigmoidf_(gi0) * tanhf(gg0);
            cst1 = sigmoidf_(gf1) * cst1 + sigmoidf_(gi1) * tanhf(gg1);
            float h0 = sigmoidf_(go0) * tanhf(cst0);
            float h1 = sigmoidf_(go1) * tanhf(cst1);

            __nv_bfloat16 bh0 = __float2bfloat16(h0), bh1 = __float2bfloat16(h1);
            __nv_bfloat16 bl0 = __float2bfloat16(h0 - __bfloat162float(bh0));
            __nv_bfloat16 bl1 = __float2bfloat16(h1 - __bfloat162float(bh1));
            __nv_bfloat162 bhv = {bh0, bh1}, blv = {bl0, bl1};

            const int hidx = gb * HH + nt * 8 + gj;
            *reinterpret_cast<__nv_bfloat162*>(hhw + hidx) = bhv;
            *reinterpret_cast<__nv_bfloat162*>(hlw + hidx) = blv;
            const size_t aidx = ((size_t)gb * TT + t) * HH + nt * 8 + gj;
            *reinterpret_cast<__nv_bfloat162*>(acth + aidx) = bhv;
            *reinterpret_cast<__nv_bfloat162*>(actl + aidx) = blv;
            if (do_state && t == TT - 1) {
                *reinterpret_cast<float2*>(outh + hidx) = make_float2(h0, h1);
                *reinterpret_cast<float2*>(outc + hidx) = make_float2(cst0, cst1);
            }
        }

        grid_barrier();
    }
}

// ---------------- launch ----------------
extern "C" void kernel_launch(void* const* d_in, const int* in_sizes, int n_in,
                              void* d_out, int out_size)
{
    const float* x      = (const float*)d_in[0];
    const float* hidden = (const float*)d_in[1];
    const float* cell   = (const float*)d_in[2];
    const float* W_ih   = (const float*)d_in[3];
    const float* W_hh   = (const float*)d_in[4];
    const float* bvec   = (const float*)d_in[5];
    const float* W_out  = (const float*)d_in[6];
    const float* b_out  = (const float*)d_in[7];
    float* out = (float*)d_out;

    float* p_gx;
    cudaGetSymbolAddress((void**)&p_gx, g_gx);
    __nv_bfloat16 *p_acth, *p_actl, *p_hh, *p_hl;
    __nv_bfloat16 *p_wih_h, *p_wih_l, *p_whh_h, *p_whh_l, *p_wout_h, *p_wout_l;
    cudaGetSymbolAddress((void**)&p_acth, g_acth);
    cudaGetSymbolAddress((void**)&p_actl, g_actl);
    cudaGetSymbolAddress((void**)&p_hh, g_hh);
    cudaGetSymbolAddress((void**)&p_hl, g_hl);
    cudaGetSymbolAddress((void**)&p_wih_h, g_wih_h);
    cudaGetSymbolAddress((void**)&p_wih_l, g_wih_l);
    cudaGetSymbolAddress((void**)&p_whh_h, g_whh_h);
    cudaGetSymbolAddress((void**)&p_whh_l, g_whh_l);
    cudaGetSymbolAddress((void**)&p_wout_h, g_wout_h);
    cudaGetSymbolAddress((void**)&p_wout_l, g_wout_l);

    cudaFuncSetAttribute(lstm_rec, cudaFuncAttributeMaxDynamicSharedMemorySize, S_TOTAL);

    const size_t LOGITS = (size_t)BB * TT * DD;
    const size_t STATE  = (size_t)BB * HH;
    const int write_state = ((size_t)out_size >= LOGITS + 2 * LNUM * STATE) ? 1 : 0;

    {
        int n4 = (LNUM * G4 * HH) / 4;
        split_kernel<<<(n4 + 255) / 256, 256>>>(W_ih, p_wih_h, p_wih_l, n4);
        split_kernel<<<(n4 + 255) / 256, 256>>>(W_hh, p_whh_h, p_whh_l, n4);
        int m4 = (DD * HH) / 4;
        split_kernel<<<(m4 + 255) / 256, 256>>>(W_out, p_wout_h, p_wout_l, m4);
    }
    {
        int n4 = (BB * TT * HH) / 4;
        split_kernel<<<(n4 + 255) / 256, 256>>>(x, p_acth, p_actl, n4);
    }

    for (int l = 0; l < LNUM; l++) {
        gemm_hmma<1><<<dim3(128, 32), 256>>>(
            p_acth, p_actl,
            p_wih_h + (size_t)l * G4 * HH, p_wih_l + (size_t)l * G4 * HH,
            bvec + (size_t)l * G4, p_gx);

        {
            int n4 = (int)(STATE / 4);
            split_kernel<<<(n4 + 255) / 256, 256>>>(hidden + (size_t)l * STATE, p_hh, p_hl, n4);
        }

        lstm_rec<<<NBLK, 256, S_TOTAL>>>(
            p_gx,
            p_whh_h + (size_t)l * G4 * HH, p_whh_l + (size_t)l * G4 * HH,
            p_hh, p_hl, p_hh + STATE, p_hl + STATE,
            cell + (size_t)l * STATE,
            p_acth, p_actl,
            out + LOGITS + (size_t)l * STATE,
            out + LOGITS + LNUM * STATE + (size_t)l * STATE,
            write_state);
    }

    gemm_hmma<0><<<dim3(128, 8), 256>>>(
        p_acth, p_actl, p_wout_h, p_wout_l, b_out, out);
}